// round 8
// baseline (speedup 1.0000x reference)
#include <cuda_runtime.h>
#include <math.h>

#define NYRS_MAX 8192
#define YPB      256                 // years per block -> 32 blocks, 8 warps/SM
#define W_YEARS  6                   // warmup years: 3 crude + 3 accurate
#define W_CRUDE  3
#define SLOTS    (YPB + W_YEARS)     // 262 year-slots incl. halo

#define PI_F 3.14159265358979323846f

__device__ __forceinline__ float fast_lg2(float x) {
    float r; asm("lg2.approx.f32 %0, %1;" : "=f"(r) : "f"(x)); return r;
}
__device__ __forceinline__ float fast_ex2(float x) {
    float r; asm("ex2.approx.f32 %0, %1;" : "=f"(r) : "f"(x)); return r;
}
__device__ __forceinline__ float fast_pow(float x, float e) {
    return fast_ex2(e * fast_lg2(x));
}
// deg-9 odd asin, |x| <= ~0.45 (err < 4e-6)
__device__ __forceinline__ float asin_poly(float x) {
    float x2 = x * x;
    float p = fmaf(x2, 0.030381944f, 0.044642857f);
    p = fmaf(x2, p, 0.075f);
    p = fmaf(x2, p, 0.16666667f);
    return fmaf(x * x2, p, x);
}
__device__ __forceinline__ float fast_acos(float x) {
    return (fabsf(x) <= 0.45f) ? (PI_F * 0.5f - asin_poly(x)) : acosf(x);
}

// ---------------- device state (no allocation) ----------------
__device__ float        g_width[NYRS_MAX];
__device__ unsigned int g_ticket = 0;

__device__ __constant__ float c_NDAYS[13] = {0,31,28,31,30,31,30,31,31,30,31,30,31};
__device__ __constant__ int   c_CDAYS[13] = {0,31,59,90,120,151,181,212,243,273,304,334,365};

__global__ void __launch_bounds__(YPB, 1)
vsl_fused_kernel(const int* __restrict__ phi_ptr,
                 const float* __restrict__ T, const float* __restrict__ P,
                 const float* __restrict__ pT1, const float* __restrict__ pT2,
                 const float* __restrict__ pM1, const float* __restrict__ pM2,
                 float* __restrict__ out, int nyrs) {
    __shared__ float sh_dtsi[365];
    __shared__ float sh_invmax;
    __shared__ float sh_L[12];
    __shared__ float sh_gE[12];
    __shared__ float sh_A [12 * SLOTS];   // month-major -> conflict-free LDS
    __shared__ float sh_B [12 * SLOTS];
    __shared__ float sh_gT[12 * SLOTS];
    __shared__ float sh_red[8];
    __shared__ float sh_bcast;
    __shared__ unsigned int sh_last;

    const int tid     = threadIdx.x;
    const int blockY0 = blockIdx.x * YPB;

    // ---- prefetch FIRST: scalars + this thread's primary slot (vectorized) ----
    const float T1 = *pT1, T2 = *pT2, M1 = *pM1, M2 = *pM2;

    const int yy0 = blockY0 - W_YEARS + tid;          // year for slot s = tid
    const bool valid0 = (yy0 >= 0) && (yy0 < nyrs);
    float4 tq0 = make_float4(0.f,0.f,0.f,0.f), tq1 = tq0, tq2 = tq0;
    float4 pq0 = tq0, pq1 = tq0, pq2 = tq0;
    if (valid0) {
        const float4* Tv = reinterpret_cast<const float4*>(T + yy0 * 12);
        const float4* Pv = reinterpret_cast<const float4*>(P + yy0 * 12);
        tq0 = Tv[0]; tq1 = Tv[1]; tq2 = Tv[2];
        pq0 = Pv[0]; pq1 = Pv[1]; pq2 = Pv[2];
    }

    const float latr  = (float)(*phi_ptr) * (PI_F / 180.0f);
    const float invDT = 1.0f / (T2 - T1);
    const float invDM = 1.0f / (M2 - M1);

    // ---- stage 1: daily insolation (overlaps the prefetch latency) ----
    const float tlat = __tanf(latr);
    const float slat = __sinf(latr);
    const float clat = __cosf(latr);
    for (int j = tid; j < 365; j += YPB) {
        float jday = (float)(j + 1);
        float ssd  = 0.39874907f * __sinf(PI_F * (jday - 80.0f) * (1.0f / 180.0f));
        float csd  = sqrtf(1.0f - ssd * ssd);
        float y    = fminf(fmaxf(-tlat * ssd * (1.0f / csd), -1.0f), 1.0f);
        float hdl  = fast_acos(y);
        float shdl = sqrtf(fmaxf(1.0f - y * y, 0.0f));
        sh_dtsi[j] = hdl * slat * ssd + clat * csd * shdl;
    }
    __syncthreads();

    if (tid < 32) {
        float mx = -1.0f;
        for (int i = tid; i < 365; i += 32) mx = fmaxf(mx, sh_dtsi[i]);
        #pragma unroll
        for (int o = 16; o > 0; o >>= 1)
            mx = fmaxf(mx, __shfl_xor_sync(0xFFFFFFFF, mx, o));
        if (tid == 0) sh_invmax = 1.0f / mx;
    }
    __syncthreads();

    if (tid < 12) {
        const int c0 = c_CDAYS[tid];
        const int c1 = c_CDAYS[tid + 1];
        float s = 0.0f;
        for (int i = c0; i < c1; i++) s += sh_dtsi[i];
        sh_gE[tid] = s * sh_invmax / (float)(c1 - c0);

        float jday_mid = (float)c0 + 0.5f * c_NDAYS[tid + 1];
        float m_star = 1.0f - tlat * __tanf(0.40908772f * __cosf(jday_mid * (PI_F / 182.625f)));
        m_star = fminf(fmaxf(m_star, 0.0f), 2.0f);
        float nhrs = 24.0f * fast_acos(1.0f - m_star) * (1.0f / PI_F);
        sh_L[tid] = c_NDAYS[tid + 1] * (1.0f / 30.0f) * (nhrs * (1.0f / 12.0f));
    }
    __syncthreads();

    // ---- stage 2: PET -> (A, B, gT) from prefetched registers ----
    // M' = clamp(A*M + B - B*(M/0.76)^4.886), A = 0.907 - ep*(0.001/0.76), B = p/1000
    {
        float t[12] = { tq0.x,tq0.y,tq0.z,tq0.w, tq1.x,tq1.y,tq1.z,tq1.w, tq2.x,tq2.y,tq2.z,tq2.w };
        float p[12] = { pq0.x,pq0.y,pq0.z,pq0.w, pq1.x,pq1.y,pq1.z,pq1.w, pq2.x,pq2.y,pq2.z,pq2.w };

        for (int s = tid; s < SLOTS; s += YPB) {
            const int yy = blockY0 - W_YEARS + s;
            const bool valid = (yy >= 0) && (yy < nyrs);
            if (s != tid) {  // halo slot for tid < W_YEARS: direct (rare) loads
                #pragma unroll
                for (int m = 0; m < 12; m++) {
                    t[m] = valid ? T[yy*12 + m] : 0.0f;
                    p[m] = valid ? P[yy*12 + m] : 0.0f;
                }
            }
            if (!valid) {
                #pragma unroll
                for (int m = 0; m < 12; m++) {
                    sh_A [m*SLOTS + s] = 1.0f;   // identity step (exact for y < W)
                    sh_B [m*SLOTS + s] = 0.0f;
                    sh_gT[m*SLOTS + s] = 0.0f;
                }
            } else {
                float I = 0.0f;
                #pragma unroll
                for (int m = 0; m < 12; m++) {
                    float is = t[m] * 0.2f;
                    if (is > 0.0f) I += fast_pow(is, 1.514f);
                }
                const float a = ((6.75e-7f * I - 7.71e-5f) * I + 0.0179f) * I + 0.49f;
                const float invI = 1.0f / I;

                #pragma unroll
                for (int m = 0; m < 12; m++) {
                    float Tm = t[m];
                    float ep;
                    if (Tm < 0.0f)        ep = 0.0f;
                    else if (Tm < 26.5f)  ep = 16.0f * sh_L[m] * fast_pow(10.0f * Tm * invI, a);
                    else                  ep = -415.85f + 32.25f * Tm - 0.43f * Tm * Tm;
                    sh_A [m*SLOTS + s] = 0.907f - ep * 1.31578947e-3f;
                    sh_B [m*SLOTS + s] = p[m] * 0.001f;
                    sh_gT[m*SLOTS + s] = fminf(fmaxf((Tm - T1) * invDT, 0.0f), 1.0f);
                }
            }
        }
    }
    __syncthreads();

    // ---- stage 3: warm-started chain + growth response ----
    const int y = blockY0 + tid;
    if (y < nyrs) {
        const float PEXP = 4.886f;
        const float POFF = 1.9345078f;        // 4.886 * log2(1/0.76)
        const float invMMAX = 1.0f / 0.76f;
        const float M1s  = M1 * invDM;

        float M = 0.2f;

        #pragma unroll
        for (int j = 0; j < W_CRUDE; j++) {
            const int s = tid + j;
            #pragma unroll
            for (int m = 0; m < 12; m++) {
                float A  = sh_A[m*SLOTS + s];
                float B  = sh_B[m*SLOTS + s];
                float r  = M * invMMAX;
                float r2 = r * r;
                float r5 = r2 * r2 * r;
                float pw = r5 * fmaf(-0.114f, r, 1.114f);
                float t  = fmaf(A, M, B);
                M = fminf(fmaxf(fmaf(-B, pw, t), 0.01f), 0.76f);
            }
        }
        #pragma unroll
        for (int j = W_CRUDE; j < W_YEARS; j++) {
            const int s = tid + j;
            #pragma unroll
            for (int m = 0; m < 12; m++) {
                float A  = sh_A[m*SLOTS + s];
                float B  = sh_B[m*SLOTS + s];
                float pw = fast_ex2(fmaf(PEXP, fast_lg2(M), POFF));
                float t  = fmaf(A, M, B);
                M = fminf(fmaxf(fmaf(-B, pw, t), 0.01f), 0.76f);
            }
        }
        float w = 0.0f;
        {
            const int s = tid + W_YEARS;
            #pragma unroll
            for (int m = 0; m < 12; m++) {
                float A  = sh_A[m*SLOTS + s];
                float B  = sh_B[m*SLOTS + s];
                float pw = fast_ex2(fmaf(PEXP, fast_lg2(M), POFF));
                float t  = fmaf(A, M, B);
                M = fminf(fmaxf(fmaf(-B, pw, t), 0.01f), 0.76f);

                float gM = fminf(fmaxf(fmaf(M, invDM, -M1s), 0.0f), 1.0f);
                w = fmaf(fminf(sh_gT[m*SLOTS + s], gM), sh_gE[m], w);
            }
        }
        g_width[y] = w;
    }

    // ---- stage 4: last-arriving block standardizes (vectorized, contiguous) ----
    __threadfence();
    __syncthreads();
    if (tid == 0) sh_last = (atomicAdd(&g_ticket, 1u) == gridDim.x - 1u);
    __syncthreads();
    if (!sh_last) return;

    const int lane = tid & 31;
    const int wid  = tid >> 5;
    const int PER  = NYRS_MAX / YPB;      // 32 contiguous years per thread
    const int base = tid * PER;

    float4 v[PER / 4];
    float s = 0.0f;
    #pragma unroll
    for (int i = 0; i < PER / 4; i++) {
        int idx = base + i * 4;
        if (idx + 3 < nyrs) {
            v[i] = *reinterpret_cast<const float4*>(&g_width[idx]);
        } else {
            v[i].x = (idx   < nyrs) ? g_width[idx]   : 0.0f;
            v[i].y = (idx+1 < nyrs) ? g_width[idx+1] : 0.0f;
            v[i].z = (idx+2 < nyrs) ? g_width[idx+2] : 0.0f;
            v[i].w = (idx+3 < nyrs) ? g_width[idx+3] : 0.0f;
        }
        s += v[i].x + v[i].y + v[i].z + v[i].w;
    }
    #pragma unroll
    for (int o = 16; o > 0; o >>= 1) s += __shfl_xor_sync(0xFFFFFFFF, s, o);
    if (lane == 0) sh_red[wid] = s;
    __syncthreads();
    if (wid == 0) {
        float t = (lane < 8) ? sh_red[lane] : 0.0f;
        #pragma unroll
        for (int o = 4; o > 0; o >>= 1) t += __shfl_xor_sync(0xFFFFFFFF, t, o);
        if (lane == 0) sh_bcast = t / (float)nyrs;
    }
    __syncthreads();
    const float mean = sh_bcast;
    __syncthreads();

    float ss = 0.0f;
    #pragma unroll
    for (int i = 0; i < PER / 4; i++) {
        int idx = base + i * 4;
        float d;
        d = v[i].x - mean; if (idx   < nyrs) ss = fmaf(d, d, ss);
        d = v[i].y - mean; if (idx+1 < nyrs) ss = fmaf(d, d, ss);
        d = v[i].z - mean; if (idx+2 < nyrs) ss = fmaf(d, d, ss);
        d = v[i].w - mean; if (idx+3 < nyrs) ss = fmaf(d, d, ss);
    }
    #pragma unroll
    for (int o = 16; o > 0; o >>= 1) ss += __shfl_xor_sync(0xFFFFFFFF, ss, o);
    if (lane == 0) sh_red[wid] = ss;
    __syncthreads();
    if (wid == 0) {
        float t = (lane < 8) ? sh_red[lane] : 0.0f;
        #pragma unroll
        for (int o = 4; o > 0; o >>= 1) t += __shfl_xor_sync(0xFFFFFFFF, t, o);
        if (lane == 0) sh_bcast = rsqrtf(t / (float)(nyrs - 1));
    }
    __syncthreads();
    const float inv = sh_bcast;

    #pragma unroll
    for (int i = 0; i < PER / 4; i++) {
        int idx = base + i * 4;
        if (idx + 3 < nyrs) {
            float4 o4;
            o4.x = (v[i].x - mean) * inv;
            o4.y = (v[i].y - mean) * inv;
            o4.z = (v[i].z - mean) * inv;
            o4.w = (v[i].w - mean) * inv;
            *reinterpret_cast<float4*>(&out[idx]) = o4;
        } else {
            if (idx   < nyrs) out[idx]   = (v[i].x - mean) * inv;
            if (idx+1 < nyrs) out[idx+1] = (v[i].y - mean) * inv;
            if (idx+2 < nyrs) out[idx+2] = (v[i].z - mean) * inv;
            if (idx+3 < nyrs) out[idx+3] = (v[i].w - mean) * inv;
        }
    }

    if (tid == 0) g_ticket = 0;   // reset for next graph replay
}

// ---------------- launch ----------------
extern "C" void kernel_launch(void* const* d_in, const int* in_sizes, int n_in,
                              void* d_out, int out_size) {
    const int*   phi = (const int*)d_in[2];
    const float* T   = (const float*)d_in[3];
    const float* P   = (const float*)d_in[4];
    const float* T1  = (const float*)d_in[5];
    const float* T2  = (const float*)d_in[6];
    const float* M1  = (const float*)d_in[7];
    const float* M2  = (const float*)d_in[8];
    float* out = (float*)d_out;

    const int nyrs = in_sizes[3] / 12;
    const int nblk = (nyrs + YPB - 1) / YPB;

    vsl_fused_kernel<<<nblk, YPB>>>(phi, T, P, T1, T2, M1, M2, out, nyrs);
}